// round 7
// baseline (speedup 1.0000x reference)
#include <cuda_runtime.h>
#include <math.h>

#define BB   8
#define TT   8192
#define DD   256
#define KK   8
#define CC   128
#define LL   (TT / CC)       // 64
#define NSEQ (BB * DD)       // 2048
#define TOUT (TT - KK + 1)   // 8185

typedef unsigned long long ull;

__device__ float4 g_trans4[CC][9][NSEQ];
__device__ float4 g_entry4[CC][2][NSEQ];
__device__ float  g_one = 1.0f;

__host__ __device__ constexpr int coff(int j) { return j * 7 - j * (j - 1) / 2; }

// ---- packed f32x2 helpers (sm_100+); max done on scalar lanes -------------
#define FMA2(d, a, b, c) \
    asm("fma.rn.f32x2 %0, %1, %2, %3;" : "=l"(d) : "l"(a), "l"(b), "l"(c))
#define PACK2(d, lo, hi) \
    asm("mov.b64 %0, {%1, %2};" : "=l"(d) : "f"(lo), "f"(hi))
#define UNPACK2(lo, hi, s) \
    asm("mov.b64 {%0, %1}, %2;" : "=f"(lo), "=f"(hi) : "l"(s))

__device__ __forceinline__ void max2s(ull& a, ull t)
{
    float alo, ahi, tlo, thi;
    UNPACK2(alo, ahi, a);
    UNPACK2(tlo, thi, t);
    ull r; PACK2(r, fmaxf(alo, tlo), fmaxf(ahi, thi));
    a = r;
}

// ---------------------------------------------------------------------------
// K1: packed-pair 36-state transform. Row k holds [v_k, m(0,k)..m(k-1,k)],
// padded to pairs; offsets O={0,1,2,4,6,9,12,16}. Dummy lanes (hi of
// P[0],P[3],P[8],P[15]) init 0, only ever consumed through a x0 multiplier.
// ---------------------------------------------------------------------------
__device__ __forceinline__ void k1_step(ull x2, const ull* w2, const ull* b2,
                                        ull one11, ull one10, ull* P)
{
    ull f2[KK];
#pragma unroll
    for (int k = 0; k < KK; k++) FMA2(f2[k], x2, w2[k], b2[k]);

    ull t;
    FMA2(t, P[12], one11, f2[7]); max2s(P[16], t);
    FMA2(t, P[13], one11, f2[7]); max2s(P[17], t);
    FMA2(t, P[14], one11, f2[7]); max2s(P[18], t);
    FMA2(t, P[15], one10, f2[7]); max2s(P[19], t);
    FMA2(t, P[9],  one11, f2[6]); max2s(P[12], t);
    FMA2(t, P[10], one11, f2[6]); max2s(P[13], t);
    FMA2(t, P[11], one11, f2[6]); max2s(P[14], t);
    max2s(P[15], f2[6]);
    FMA2(t, P[6], one11, f2[5]); max2s(P[9],  t);
    FMA2(t, P[7], one11, f2[5]); max2s(P[10], t);
    FMA2(t, P[8], one10, f2[5]); max2s(P[11], t);
    FMA2(t, P[4], one11, f2[4]); max2s(P[6], t);
    FMA2(t, P[5], one11, f2[4]); max2s(P[7], t);
    max2s(P[8], f2[4]);
    FMA2(t, P[2], one11, f2[3]); max2s(P[4], t);
    FMA2(t, P[3], one10, f2[3]); max2s(P[5], t);
    FMA2(t, P[1], one11, f2[2]); max2s(P[2], t);
    max2s(P[3], f2[2]);
    FMA2(t, P[0], one10, f2[1]); max2s(P[1], t);
    max2s(P[0], f2[0]);
}

__global__ void __launch_bounds__(64) k1_transform(
    const float* __restrict__ X,
    const float* __restrict__ W,
    const float* __restrict__ Bv)
{
    int tid = blockIdx.x * blockDim.x + threadIdx.x;   // 0 .. NSEQ*(CC-1)-1
    int d = tid & (DD - 1);
    int q = tid >> 8;
    int b = q & (BB - 1);
    int c = q >> 3;            // 0 .. CC-2 (last chunk's transform unused)
    int s = b * DD + d;

    ull w2[KK], b2[KK];
#pragma unroll
    for (int k = 0; k < KK; k++) {
        float wv = __ldg(W + k * DD + d);
        float bv = __ldg(Bv + k * DD + d);
        PACK2(w2[k], wv, wv);
        PACK2(b2[k], bv, bv);
    }

    const float NI = -INFINITY;
    ull one11, one10, initRR, initR0;
    PACK2(one11, 1.0f, 1.0f);
    PACK2(one10, 1.0f, 0.0f);
    PACK2(initRR, NI, NI);
    PACK2(initR0, NI, 0.0f);

    ull P[20];
#pragma unroll
    for (int e = 0; e < 20; e++) P[e] = initRR;
    P[0] = initR0; P[3] = initR0; P[8] = initR0; P[15] = initR0;

    const float* xp = X + ((size_t)b * TT + (size_t)c * LL) * DD + d;

    float xb[8];
#pragma unroll
    for (int j = 0; j < 8; j++) xb[j] = __ldg(xp + (size_t)j * DD);
    xp += (size_t)8 * DD;

    for (int ii = 0; ii < LL - 8; ii += 8) {
#pragma unroll
        for (int j = 0; j < 8; j++) {
            ull x2; PACK2(x2, xb[j], xb[j]);
            xb[j] = __ldg(xp + (size_t)j * DD);
            k1_step(x2, w2, b2, one11, one10, P);
        }
        xp += (size_t)8 * DD;
    }
#pragma unroll
    for (int j = 0; j < 8; j++) {
        ull x2; PACK2(x2, xb[j], xb[j]);
        k1_step(x2, w2, b2, one11, one10, P);
    }

    // unpack rows back to the [v(8), m(28)] layout used by K2
    const int O[8] = {0, 1, 2, 4, 6, 9, 12, 16};
    float t[36];
#pragma unroll
    for (int k = 0; k < KK; k++) {
#pragma unroll
        for (int i = 0; i <= k / 2; i++) {
            float lo, hi;
            UNPACK2(lo, hi, P[O[k] + i]);
            int p0 = 2 * i, p1 = 2 * i + 1;
            t[(p0 == 0) ? k : (8 + coff(p0 - 1) + k - p0)] = lo;
            if (p1 <= k)
                t[(p1 == 0) ? k : (8 + coff(p1 - 1) + k - p1)] = hi;
        }
    }
#pragma unroll
    for (int g = 0; g < 9; g++)
        g_trans4[c][g][s] = make_float4(t[4 * g], t[4 * g + 1],
                                        t[4 * g + 2], t[4 * g + 3]);
}

// ---------------------------------------------------------------------------
// K2: sequential compose per sequence (float4 loads, one-chunk prefetch).
// ---------------------------------------------------------------------------
__global__ void __launch_bounds__(32) k2_compose()
{
    int s = blockIdx.x * blockDim.x + threadIdx.x;
    const float NI = -INFINITY;
    const float one = g_one;

    float v[KK];
#pragma unroll
    for (int k = 0; k < KK; k++) v[k] = NI;

    float cur[36];
#pragma unroll
    for (int g = 0; g < 9; g++) {
        float4 qd = g_trans4[0][g][s];
        cur[4 * g] = qd.x; cur[4 * g + 1] = qd.y;
        cur[4 * g + 2] = qd.z; cur[4 * g + 3] = qd.w;
    }

    for (int c = 0; c < CC; c++) {
        g_entry4[c][0][s] = make_float4(v[0], v[1], v[2], v[3]);
        g_entry4[c][1][s] = make_float4(v[4], v[5], v[6], v[7]);
        if (c == CC - 1) break;

        float nxt[36];
        if (c + 1 < CC - 1) {
#pragma unroll
            for (int g = 0; g < 9; g++) {
                float4 qd = g_trans4[c + 1][g][s];
                nxt[4 * g] = qd.x; nxt[4 * g + 1] = qd.y;
                nxt[4 * g + 2] = qd.z; nxt[4 * g + 3] = qd.w;
            }
        } else {
#pragma unroll
            for (int e = 0; e < 36; e++) nxt[e] = NI;
        }

        float nv[KK];
#pragma unroll
        for (int k = 0; k < KK; k++) {
            float best = fmaxf(cur[k], v[k]);
#pragma unroll
            for (int j = 0; j < k; j++)
                best = fmaxf(best, fmaf(v[j], one, cur[8 + coff(j) + k - j - 1]));
            nv[k] = best;
        }
#pragma unroll
        for (int k = 0; k < KK; k++) v[k] = nv[k];
#pragma unroll
        for (int e = 0; e < 36; e++) cur[e] = nxt[e];
    }
}

// ---------------------------------------------------------------------------
// K3: re-scan with exact entry states, TWO adjacent sequences per thread
// packed into f32x2 lanes; maxes scalar on lanes.
// ---------------------------------------------------------------------------
__device__ __forceinline__ void k3_step(ull x2, const ull* w2, const ull* b2,
                                        ull one11, ull* v2)
{
    ull f2[KK];
#pragma unroll
    for (int k = 0; k < KK; k++) FMA2(f2[k], x2, w2[k], b2[k]);
    ull t;
#pragma unroll
    for (int k = KK - 1; k >= 1; k--) {
        FMA2(t, v2[k - 1], one11, f2[k]);
        max2s(v2[k], t);
    }
    max2s(v2[0], f2[0]);
}

__global__ void __launch_bounds__(128) k3_emit(
    const float* __restrict__ X,
    const float* __restrict__ W,
    const float* __restrict__ Bv,
    float* __restrict__ out)
{
    int tid = blockIdx.x * blockDim.x + threadIdx.x;   // 0 .. NSEQ/2*CC-1
    int d = (tid & 127) << 1;          // even d; thread covers d, d+1
    int q = tid >> 7;
    int b = q & (BB - 1);
    int c = q >> 3;
    int s = b * DD + d;

    ull one11; PACK2(one11, 1.0f, 1.0f);

    ull w2[KK], b2[KK];
#pragma unroll
    for (int k = 0; k < KK; k++) {
        w2[k] = __ldg((const ull*)(W  + k * DD + d));
        b2[k] = __ldg((const ull*)(Bv + k * DD + d));
    }

    ull v2[KK];
    {
        float4 a0 = g_entry4[c][0][s];
        float4 a1 = g_entry4[c][1][s];
        float4 c0 = g_entry4[c][0][s + 1];
        float4 c1 = g_entry4[c][1][s + 1];
        PACK2(v2[0], a0.x, c0.x); PACK2(v2[1], a0.y, c0.y);
        PACK2(v2[2], a0.z, c0.z); PACK2(v2[3], a0.w, c0.w);
        PACK2(v2[4], a1.x, c1.x); PACK2(v2[5], a1.y, c1.y);
        PACK2(v2[6], a1.z, c1.z); PACK2(v2[7], a1.w, c1.w);
    }

    const float* xp = X + ((size_t)b * TT + (size_t)c * LL) * DD + d;

    ull xb[8];
#pragma unroll
    for (int j = 0; j < 8; j++) xb[j] = __ldg((const ull*)(xp + (size_t)j * DD));
    xp += (size_t)8 * DD;

    if (c == 0) {
        float* ob = out + (size_t)b * TOUT * DD + d;
        for (int ii = 0; ii < LL - 8; ii += 8) {
#pragma unroll
            for (int j = 0; j < 8; j++) {
                ull x2 = xb[j];
                xb[j] = __ldg((const ull*)(xp + (size_t)j * DD));
                k3_step(x2, w2, b2, one11, v2);
                int i = ii + j;
                if (i >= KK - 1)
                    *(ull*)(ob + (size_t)(i - (KK - 1)) * DD) = v2[KK - 1];
            }
            xp += (size_t)8 * DD;
        }
#pragma unroll
        for (int j = 0; j < 8; j++) {
            k3_step(xb[j], w2, b2, one11, v2);
            *(ull*)(ob + (size_t)(LL - 8 + j - (KK - 1)) * DD) = v2[KK - 1];
        }
    } else {
        float* op = out + ((size_t)b * TOUT + (size_t)(c * LL - (KK - 1))) * DD + d;
        for (int ii = 0; ii < LL - 8; ii += 8) {
#pragma unroll
            for (int j = 0; j < 8; j++) {
                ull x2 = xb[j];
                xb[j] = __ldg((const ull*)(xp + (size_t)j * DD));
                k3_step(x2, w2, b2, one11, v2);
                *(ull*)(op + (size_t)(ii + j) * DD) = v2[KK - 1];
            }
            xp += (size_t)8 * DD;
        }
#pragma unroll
        for (int j = 0; j < 8; j++) {
            k3_step(xb[j], w2, b2, one11, v2);
            *(ull*)(op + (size_t)(LL - 8 + j) * DD) = v2[KK - 1];
        }
    }
}

// ---------------------------------------------------------------------------
extern "C" void kernel_launch(void* const* d_in, const int* in_sizes, int n_in,
                              void* d_out, int out_size)
{
    const float* X  = (const float*)d_in[0];
    const float* W  = (const float*)d_in[1];
    const float* Bv = (const float*)d_in[2];
    float* out = (float*)d_out;

    k1_transform<<<(NSEQ * (CC - 1)) / 64, 64>>>(X, W, Bv);
    k2_compose<<<NSEQ / 32, 32>>>();
    k3_emit<<<(NSEQ / 2 * CC) / 128, 128>>>(X, W, Bv, out);
}

// round 8
// speedup vs baseline: 1.3274x; 1.3274x over previous
#include <cuda_runtime.h>
#include <math.h>

#define BB   8
#define TT   8192
#define DD   256
#define KK   8
#define CC   128
#define LL   (TT / CC)       // 64
#define NSEQ (BB * DD)       // 2048
#define TOUT (TT - KK + 1)   // 8185
#define QD   4               // K2 prefetch depth (chunks in flight)

typedef unsigned long long ull;

__device__ float4 g_trans4[CC][9][NSEQ];
__device__ float4 g_entry4[CC][2][NSEQ];

__host__ __device__ constexpr int coff(int j) { return j * 7 - j * (j - 1) / 2; }

// ---- packed f32x2 helpers (sm_100+); max done on scalar lanes -------------
#define FMA2(d, a, b, c) \
    asm("fma.rn.f32x2 %0, %1, %2, %3;" : "=l"(d) : "l"(a), "l"(b), "l"(c))
#define PACK2(d, lo, hi) \
    asm("mov.b64 %0, {%1, %2};" : "=l"(d) : "f"(lo), "f"(hi))
#define UNPACK2(lo, hi, s) \
    asm("mov.b64 {%0, %1}, %2;" : "=f"(lo), "=f"(hi) : "l"(s))

__device__ __forceinline__ void max2s(ull& a, ull t)
{
    float alo, ahi, tlo, thi;
    UNPACK2(alo, ahi, a);
    UNPACK2(tlo, thi, t);
    ull r; PACK2(r, fmaxf(alo, tlo), fmaxf(ahi, thi));
    a = r;
}

// ---------------------------------------------------------------------------
// K1: packed-pair 36-state transform. Row k holds [v_k, m(0,k)..m(k-1,k)],
// padded to pairs; offsets O={0,1,2,4,6,9,12,16}. Dummy lanes (hi of
// P[0],P[3],P[8],P[15]) init 0, only ever consumed through a x0 multiplier.
// ---------------------------------------------------------------------------
__device__ __forceinline__ void k1_step(ull x2, const ull* w2, const ull* b2,
                                        ull one11, ull one10, ull* P)
{
    ull f2[KK];
#pragma unroll
    for (int k = 0; k < KK; k++) FMA2(f2[k], x2, w2[k], b2[k]);

    ull t;
    FMA2(t, P[12], one11, f2[7]); max2s(P[16], t);
    FMA2(t, P[13], one11, f2[7]); max2s(P[17], t);
    FMA2(t, P[14], one11, f2[7]); max2s(P[18], t);
    FMA2(t, P[15], one10, f2[7]); max2s(P[19], t);
    FMA2(t, P[9],  one11, f2[6]); max2s(P[12], t);
    FMA2(t, P[10], one11, f2[6]); max2s(P[13], t);
    FMA2(t, P[11], one11, f2[6]); max2s(P[14], t);
    max2s(P[15], f2[6]);
    FMA2(t, P[6], one11, f2[5]); max2s(P[9],  t);
    FMA2(t, P[7], one11, f2[5]); max2s(P[10], t);
    FMA2(t, P[8], one10, f2[5]); max2s(P[11], t);
    FMA2(t, P[4], one11, f2[4]); max2s(P[6], t);
    FMA2(t, P[5], one11, f2[4]); max2s(P[7], t);
    max2s(P[8], f2[4]);
    FMA2(t, P[2], one11, f2[3]); max2s(P[4], t);
    FMA2(t, P[3], one10, f2[3]); max2s(P[5], t);
    FMA2(t, P[1], one11, f2[2]); max2s(P[2], t);
    max2s(P[3], f2[2]);
    FMA2(t, P[0], one10, f2[1]); max2s(P[1], t);
    max2s(P[0], f2[0]);
}

__global__ void __launch_bounds__(64) k1_transform(
    const float* __restrict__ X,
    const float* __restrict__ W,
    const float* __restrict__ Bv)
{
    int tid = blockIdx.x * blockDim.x + threadIdx.x;   // 0 .. NSEQ*(CC-1)-1
    int d = tid & (DD - 1);
    int q = tid >> 8;
    int b = q & (BB - 1);
    int c = q >> 3;            // 0 .. CC-2 (last chunk's transform unused)
    int s = b * DD + d;

    ull w2[KK], b2[KK];
#pragma unroll
    for (int k = 0; k < KK; k++) {
        float wv = __ldg(W + k * DD + d);
        float bv = __ldg(Bv + k * DD + d);
        PACK2(w2[k], wv, wv);
        PACK2(b2[k], bv, bv);
    }

    const float NI = -INFINITY;
    ull one11, one10, initRR, initR0;
    PACK2(one11, 1.0f, 1.0f);
    PACK2(one10, 1.0f, 0.0f);
    PACK2(initRR, NI, NI);
    PACK2(initR0, NI, 0.0f);

    ull P[20];
#pragma unroll
    for (int e = 0; e < 20; e++) P[e] = initRR;
    P[0] = initR0; P[3] = initR0; P[8] = initR0; P[15] = initR0;

    const float* xp = X + ((size_t)b * TT + (size_t)c * LL) * DD + d;

    float xb[8];
#pragma unroll
    for (int j = 0; j < 8; j++) xb[j] = __ldg(xp + (size_t)j * DD);
    xp += (size_t)8 * DD;

    for (int ii = 0; ii < LL - 8; ii += 8) {
#pragma unroll
        for (int j = 0; j < 8; j++) {
            ull x2; PACK2(x2, xb[j], xb[j]);
            xb[j] = __ldg(xp + (size_t)j * DD);
            k1_step(x2, w2, b2, one11, one10, P);
        }
        xp += (size_t)8 * DD;
    }
#pragma unroll
    for (int j = 0; j < 8; j++) {
        ull x2; PACK2(x2, xb[j], xb[j]);
        k1_step(x2, w2, b2, one11, one10, P);
    }

    // unpack rows back to the [v(8), m(28)] layout used by K2
    const int O[8] = {0, 1, 2, 4, 6, 9, 12, 16};
    float t[36];
#pragma unroll
    for (int k = 0; k < KK; k++) {
#pragma unroll
        for (int i = 0; i <= k / 2; i++) {
            float lo, hi;
            UNPACK2(lo, hi, P[O[k] + i]);
            int p0 = 2 * i, p1 = 2 * i + 1;
            t[(p0 == 0) ? k : (8 + coff(p0 - 1) + k - p0)] = lo;
            if (p1 <= k)
                t[(p1 == 0) ? k : (8 + coff(p1 - 1) + k - p1)] = hi;
        }
    }
#pragma unroll
    for (int g = 0; g < 9; g++)
        g_trans4[c][g][s] = make_float4(t[4 * g], t[4 * g + 1],
                                        t[4 * g + 2], t[4 * g + 3]);
}

// ---------------------------------------------------------------------------
// K2: warp-parallel compose. 8 threads per sequence (thread = state k).
// nv[k] = max(local_k, v_k, max_{j<k}(v_j + M[j][k])); v broadcast via shfl.
// Depth-QD register prefetch of the per-thread column hides L2 latency.
// ---------------------------------------------------------------------------
__global__ void __launch_bounds__(128) k2_compose()
{
    int t = blockIdx.x * blockDim.x + threadIdx.x;   // 0 .. NSEQ*8-1
    int k = t & 7;
    int s = t >> 3;
    int lane = threadIdx.x & 31;
    int gbase = lane & 24;        // first lane of this thread's 8-group
    const float NI = -INFINITY;

    // element index (into the 36-float record) of M[j][k] for j<k
    int em[7];
#pragma unroll
    for (int j = 0; j < 7; j++)
        em[j] = 8 + coff(j) + k - j - 1;   // only valid when j < k

    const float* base = (const float*)g_trans4;
    // t[e] of (chunk c, seq s) lives at base + ((c*9 + e/4)*NSEQ + s)*4 + e%4

    float pl[QD];
    float pm[QD][7];
#pragma unroll
    for (int u = 0; u < QD; u++) {
        int c = u;
        bool ok = (c <= CC - 2);
        pl[u] = ok ? __ldg(base + (((size_t)c * 9 + (k >> 2)) * NSEQ + s) * 4 + (k & 3)) : NI;
#pragma unroll
        for (int j = 0; j < 7; j++)
            pm[u][j] = (ok && j < k)
                ? __ldg(base + (((size_t)c * 9 + (em[j] >> 2)) * NSEQ + s) * 4 + (em[j] & 3))
                : NI;
    }

    float* ebase = (float*)g_entry4;
    float v = NI;

    for (int cb = 0; cb < CC; cb += QD) {
#pragma unroll
        for (int u = 0; u < QD; u++) {
            int c = cb + u;
            // record entry state of chunk c
            ebase[(((size_t)c * 2 + (k >> 2)) * NSEQ + s) * 4 + (k & 3)] = v;
            if (c == CC - 1) return;   // uniform across warp

            // broadcast v across the 8-group
            float vj[8];
#pragma unroll
            for (int j = 0; j < 8; j++)
                vj[j] = __shfl_sync(0xffffffffu, v, gbase + j);

            float nv = fmaxf(pl[u], v);
#pragma unroll
            for (int j = 0; j < 7; j++)
                nv = fmaxf(nv, vj[j] + pm[u][j]);   // pm = -inf where unused
            v = nv;

            // prefetch chunk c+QD into this slot
            int cn = c + QD;
            bool ok = (cn <= CC - 2);
            pl[u] = ok ? __ldg(base + (((size_t)cn * 9 + (k >> 2)) * NSEQ + s) * 4 + (k & 3)) : NI;
#pragma unroll
            for (int j = 0; j < 7; j++)
                pm[u][j] = (ok && j < k)
                    ? __ldg(base + (((size_t)cn * 9 + (em[j] >> 2)) * NSEQ + s) * 4 + (em[j] & 3))
                    : NI;
        }
    }
}

// ---------------------------------------------------------------------------
// K3: re-scan with exact entry states, TWO adjacent sequences per thread
// packed into f32x2 lanes; maxes scalar on lanes.
// ---------------------------------------------------------------------------
__device__ __forceinline__ void k3_step(ull x2, const ull* w2, const ull* b2,
                                        ull one11, ull* v2)
{
    ull f2[KK];
#pragma unroll
    for (int k = 0; k < KK; k++) FMA2(f2[k], x2, w2[k], b2[k]);
    ull t;
#pragma unroll
    for (int k = KK - 1; k >= 1; k--) {
        FMA2(t, v2[k - 1], one11, f2[k]);
        max2s(v2[k], t);
    }
    max2s(v2[0], f2[0]);
}

__global__ void __launch_bounds__(128) k3_emit(
    const float* __restrict__ X,
    const float* __restrict__ W,
    const float* __restrict__ Bv,
    float* __restrict__ out)
{
    int tid = blockIdx.x * blockDim.x + threadIdx.x;   // 0 .. NSEQ/2*CC-1
    int d = (tid & 127) << 1;          // even d; thread covers d, d+1
    int q = tid >> 7;
    int b = q & (BB - 1);
    int c = q >> 3;
    int s = b * DD + d;

    ull one11; PACK2(one11, 1.0f, 1.0f);

    ull w2[KK], b2[KK];
#pragma unroll
    for (int k = 0; k < KK; k++) {
        w2[k] = __ldg((const ull*)(W  + k * DD + d));
        b2[k] = __ldg((const ull*)(Bv + k * DD + d));
    }

    ull v2[KK];
    {
        float4 a0 = g_entry4[c][0][s];
        float4 a1 = g_entry4[c][1][s];
        float4 c0 = g_entry4[c][0][s + 1];
        float4 c1 = g_entry4[c][1][s + 1];
        PACK2(v2[0], a0.x, c0.x); PACK2(v2[1], a0.y, c0.y);
        PACK2(v2[2], a0.z, c0.z); PACK2(v2[3], a0.w, c0.w);
        PACK2(v2[4], a1.x, c1.x); PACK2(v2[5], a1.y, c1.y);
        PACK2(v2[6], a1.z, c1.z); PACK2(v2[7], a1.w, c1.w);
    }

    const float* xp = X + ((size_t)b * TT + (size_t)c * LL) * DD + d;

    ull xb[8];
#pragma unroll
    for (int j = 0; j < 8; j++) xb[j] = __ldg((const ull*)(xp + (size_t)j * DD));
    xp += (size_t)8 * DD;

    if (c == 0) {
        float* ob = out + (size_t)b * TOUT * DD + d;
        for (int ii = 0; ii < LL - 8; ii += 8) {
#pragma unroll
            for (int j = 0; j < 8; j++) {
                ull x2 = xb[j];
                xb[j] = __ldg((const ull*)(xp + (size_t)j * DD));
                k3_step(x2, w2, b2, one11, v2);
                int i = ii + j;
                if (i >= KK - 1)
                    *(ull*)(ob + (size_t)(i - (KK - 1)) * DD) = v2[KK - 1];
            }
            xp += (size_t)8 * DD;
        }
#pragma unroll
        for (int j = 0; j < 8; j++) {
            k3_step(xb[j], w2, b2, one11, v2);
            *(ull*)(ob + (size_t)(LL - 8 + j - (KK - 1)) * DD) = v2[KK - 1];
        }
    } else {
        float* op = out + ((size_t)b * TOUT + (size_t)(c * LL - (KK - 1))) * DD + d;
        for (int ii = 0; ii < LL - 8; ii += 8) {
#pragma unroll
            for (int j = 0; j < 8; j++) {
                ull x2 = xb[j];
                xb[j] = __ldg((const ull*)(xp + (size_t)j * DD));
                k3_step(x2, w2, b2, one11, v2);
                *(ull*)(op + (size_t)(ii + j) * DD) = v2[KK - 1];
            }
            xp += (size_t)8 * DD;
        }
#pragma unroll
        for (int j = 0; j < 8; j++) {
            k3_step(xb[j], w2, b2, one11, v2);
            *(ull*)(op + (size_t)(LL - 8 + j) * DD) = v2[KK - 1];
        }
    }
}

// ---------------------------------------------------------------------------
extern "C" void kernel_launch(void* const* d_in, const int* in_sizes, int n_in,
                              void* d_out, int out_size)
{
    const float* X  = (const float*)d_in[0];
    const float* W  = (const float*)d_in[1];
    const float* Bv = (const float*)d_in[2];
    float* out = (float*)d_out;

    k1_transform<<<(NSEQ * (CC - 1)) / 64, 64>>>(X, W, Bv);
    k2_compose<<<(NSEQ * 8) / 128, 128>>>();
    k3_emit<<<(NSEQ / 2 * CC) / 128, 128>>>(X, W, Bv, out);
}

// round 9
// speedup vs baseline: 1.3824x; 1.0414x over previous
#include <cuda_runtime.h>
#include <math.h>

#define BB   8
#define TT   8192
#define DD   256
#define KK   8
#define CC   128
#define LL   (TT / CC)       // 64
#define NSEQ (BB * DD)       // 2048
#define TOUT (TT - KK + 1)   // 8185
#define QD   4               // K2 prefetch depth

typedef unsigned long long ull;

__device__ float4 g_trans4[CC][9][NSEQ];
__device__ float4 g_entry4[CC][2][NSEQ];
__device__ float  g_one = 1.0f;

__host__ __device__ constexpr int coff(int j) { return j * 7 - j * (j - 1) / 2; }

// flat float index of transform element e for (chunk c, seq s)
__device__ __forceinline__ size_t tidx(int c, int e, int s)
{
    return (((size_t)c * 9 + (e >> 2)) * NSEQ + s) * 4 + (e & 3);
}

// ---------------------------------------------------------------------------
// K1: column-split transform. Two warps per 32 sequences of one chunk:
//   role 0 (warp 0): local vector v[0..7] + matrix cols 3,4,5,6 (18 states)
//   role 1 (warp 1): matrix cols 0,1,2                         (18 states)
// All chains are independent DPs sharing f[k] = x*w[k]+b[k].
// ---------------------------------------------------------------------------
__global__ void __launch_bounds__(64) k1_transform(
    const float* __restrict__ X,
    const float* __restrict__ W,
    const float* __restrict__ Bv)
{
    int lane = threadIdx.x & 31;
    int role = threadIdx.x >> 5;           // 0 = A, 1 = B
    int pid  = blockIdx.x * 32 + lane;     // 0 .. NSEQ*(CC-1)-1
    int d = pid & (DD - 1);
    int q = pid >> 8;
    int b = q & (BB - 1);
    int c = q >> 3;                        // 0 .. CC-2
    int s = b * DD + d;

    const float one = g_one;
    const float NI = -INFINITY;

    float wk[KK], bk[KK];
#pragma unroll
    for (int k = 0; k < KK; k++) {
        wk[k] = __ldg(W + k * DD + d);
        bk[k] = __ldg(Bv + k * DD + d);
    }

    const float* xp = X + ((size_t)b * TT + (size_t)c * LL) * DD + d;
    float* tb = (float*)g_trans4;

    float xb[8];
#pragma unroll
    for (int j = 0; j < 8; j++) xb[j] = __ldg(xp + (size_t)j * DD);
    xp += (size_t)8 * DD;

    if (role == 0) {
        float v[8], m3[4], m4[3], m5[2], m6;
#pragma unroll
        for (int k = 0; k < 8; k++) v[k] = NI;
#pragma unroll
        for (int i = 0; i < 4; i++) m3[i] = NI;
#pragma unroll
        for (int i = 0; i < 3; i++) m4[i] = NI;
        m5[0] = NI; m5[1] = NI; m6 = NI;

#define A_STEP(x) do {                                                   \
        float f[8];                                                      \
        _Pragma("unroll")                                                \
        for (int k = 0; k < 8; k++) f[k] = fmaf((x), wk[k], bk[k]);      \
        _Pragma("unroll")                                                \
        for (int k = 7; k >= 1; k--) v[k] = fmaxf(v[k], fmaf(v[k-1], one, f[k])); \
        v[0] = fmaxf(v[0], f[0]);                                        \
        m3[3] = fmaxf(m3[3], fmaf(m3[2], one, f[7]));                    \
        m3[2] = fmaxf(m3[2], fmaf(m3[1], one, f[6]));                    \
        m3[1] = fmaxf(m3[1], fmaf(m3[0], one, f[5]));                    \
        m3[0] = fmaxf(m3[0], f[4]);                                      \
        m4[2] = fmaxf(m4[2], fmaf(m4[1], one, f[7]));                    \
        m4[1] = fmaxf(m4[1], fmaf(m4[0], one, f[6]));                    \
        m4[0] = fmaxf(m4[0], f[5]);                                      \
        m5[1] = fmaxf(m5[1], fmaf(m5[0], one, f[7]));                    \
        m5[0] = fmaxf(m5[0], f[6]);                                      \
        m6    = fmaxf(m6, f[7]);                                         \
    } while (0)

        for (int ii = 0; ii < LL - 8; ii += 8) {
#pragma unroll
            for (int j = 0; j < 8; j++) {
                float x = xb[j];
                xb[j] = __ldg(xp + (size_t)j * DD);
                A_STEP(x);
            }
            xp += (size_t)8 * DD;
        }
#pragma unroll
        for (int j = 0; j < 8; j++) A_STEP(xb[j]);

#pragma unroll
        for (int k = 0; k < 8; k++) tb[tidx(c, k, s)] = v[k];
#pragma unroll
        for (int i = 0; i < 4; i++) tb[tidx(c, 8 + coff(3) + i, s)] = m3[i];
#pragma unroll
        for (int i = 0; i < 3; i++) tb[tidx(c, 8 + coff(4) + i, s)] = m4[i];
#pragma unroll
        for (int i = 0; i < 2; i++) tb[tidx(c, 8 + coff(5) + i, s)] = m5[i];
        tb[tidx(c, 8 + coff(6), s)] = m6;
    } else {
        float m0[7], m1[6], m2[5];
#pragma unroll
        for (int i = 0; i < 7; i++) m0[i] = NI;
#pragma unroll
        for (int i = 0; i < 6; i++) m1[i] = NI;
#pragma unroll
        for (int i = 0; i < 5; i++) m2[i] = NI;

#define B_STEP(x) do {                                                   \
        float f[8];                                                      \
        _Pragma("unroll")                                                \
        for (int k = 1; k < 8; k++) f[k] = fmaf((x), wk[k], bk[k]);      \
        _Pragma("unroll")                                                \
        for (int i = 6; i >= 1; i--) m0[i] = fmaxf(m0[i], fmaf(m0[i-1], one, f[i+1])); \
        m0[0] = fmaxf(m0[0], f[1]);                                      \
        _Pragma("unroll")                                                \
        for (int i = 5; i >= 1; i--) m1[i] = fmaxf(m1[i], fmaf(m1[i-1], one, f[i+2])); \
        m1[0] = fmaxf(m1[0], f[2]);                                      \
        _Pragma("unroll")                                                \
        for (int i = 4; i >= 1; i--) m2[i] = fmaxf(m2[i], fmaf(m2[i-1], one, f[i+3])); \
        m2[0] = fmaxf(m2[0], f[3]);                                      \
    } while (0)

        for (int ii = 0; ii < LL - 8; ii += 8) {
#pragma unroll
            for (int j = 0; j < 8; j++) {
                float x = xb[j];
                xb[j] = __ldg(xp + (size_t)j * DD);
                B_STEP(x);
            }
            xp += (size_t)8 * DD;
        }
#pragma unroll
        for (int j = 0; j < 8; j++) B_STEP(xb[j]);

#pragma unroll
        for (int i = 0; i < 7; i++) tb[tidx(c, 8 + coff(0) + i, s)] = m0[i];
#pragma unroll
        for (int i = 0; i < 6; i++) tb[tidx(c, 8 + coff(1) + i, s)] = m1[i];
#pragma unroll
        for (int i = 0; i < 5; i++) tb[tidx(c, 8 + coff(2) + i, s)] = m2[i];
    }
}

// ---------------------------------------------------------------------------
// K2: warp-parallel compose. 8 threads per sequence (thread = state k).
// nv[k] = max(local_k, v_k, max_{j<k}(v_j + M[j][k])); v broadcast via shfl.
// Depth-QD register prefetch of the per-thread column hides L2 latency.
// ---------------------------------------------------------------------------
__global__ void __launch_bounds__(128) k2_compose()
{
    int t = blockIdx.x * blockDim.x + threadIdx.x;   // 0 .. NSEQ*8-1
    int k = t & 7;
    int s = t >> 3;
    int lane = threadIdx.x & 31;
    int gbase = lane & 24;
    const float NI = -INFINITY;

    int em[7];
#pragma unroll
    for (int j = 0; j < 7; j++)
        em[j] = 8 + coff(j) + k - j - 1;   // valid only when j < k

    const float* base = (const float*)g_trans4;

    float pl[QD];
    float pm[QD][7];
#pragma unroll
    for (int u = 0; u < QD; u++) {
        int c = u;
        bool ok = (c <= CC - 2);
        pl[u] = ok ? __ldg(base + tidx(c, k, s)) : NI;
#pragma unroll
        for (int j = 0; j < 7; j++)
            pm[u][j] = (ok && j < k) ? __ldg(base + tidx(c, em[j], s)) : NI;
    }

    float* ebase = (float*)g_entry4;
    float v = NI;

    for (int cb = 0; cb < CC; cb += QD) {
#pragma unroll
        for (int u = 0; u < QD; u++) {
            int c = cb + u;
            ebase[(((size_t)c * 2 + (k >> 2)) * NSEQ + s) * 4 + (k & 3)] = v;
            if (c == CC - 1) return;

            float vj[8];
#pragma unroll
            for (int j = 0; j < 8; j++)
                vj[j] = __shfl_sync(0xffffffffu, v, gbase + j);

            float nv = fmaxf(pl[u], v);
#pragma unroll
            for (int j = 0; j < 7; j++)
                nv = fmaxf(nv, vj[j] + pm[u][j]);
            v = nv;

            int cn = c + QD;
            bool ok = (cn <= CC - 2);
            pl[u] = ok ? __ldg(base + tidx(cn, k, s)) : NI;
#pragma unroll
            for (int j = 0; j < 7; j++)
                pm[u][j] = (ok && j < k) ? __ldg(base + tidx(cn, em[j], s)) : NI;
        }
    }
}

// ---------------------------------------------------------------------------
// K3: scalar re-scan, one thread per (chunk, seq); 8-deep x prefetch.
// ---------------------------------------------------------------------------
__device__ __forceinline__ void scan_step(float x, float one, const float* wk,
                                          const float* bk, float* v)
{
    float f[KK];
#pragma unroll
    for (int k = 0; k < KK; k++) f[k] = fmaf(x, wk[k], bk[k]);
#pragma unroll
    for (int k = KK - 1; k >= 1; k--)
        v[k] = fmaxf(v[k], fmaf(v[k - 1], one, f[k]));
    v[0] = fmaxf(v[0], f[0]);
}

__global__ void __launch_bounds__(128) k3_emit(
    const float* __restrict__ X,
    const float* __restrict__ W,
    const float* __restrict__ Bv,
    float* __restrict__ out)
{
    int tid = blockIdx.x * blockDim.x + threadIdx.x;   // 0 .. NSEQ*CC-1
    int d = tid & (DD - 1);
    int q = tid >> 8;
    int b = q & (BB - 1);
    int c = q >> 3;
    int s = b * DD + d;

    const float one = g_one;

    float wk[KK], bk[KK];
#pragma unroll
    for (int k = 0; k < KK; k++) {
        wk[k] = __ldg(W + k * DD + d);
        bk[k] = __ldg(Bv + k * DD + d);
    }

    const float* ebase = (const float*)g_entry4;
    float v[KK];
#pragma unroll
    for (int k = 0; k < KK; k++)
        v[k] = __ldg(ebase + (((size_t)c * 2 + (k >> 2)) * NSEQ + s) * 4 + (k & 3));

    const float* xp = X + ((size_t)b * TT + (size_t)c * LL) * DD + d;

    float xb[8];
#pragma unroll
    for (int j = 0; j < 8; j++) xb[j] = __ldg(xp + (size_t)j * DD);
    xp += (size_t)8 * DD;

    if (c == 0) {
        float* ob = out + (size_t)b * TOUT * DD + d;
        for (int ii = 0; ii < LL - 8; ii += 8) {
#pragma unroll
            for (int j = 0; j < 8; j++) {
                float x = xb[j];
                xb[j] = __ldg(xp + (size_t)j * DD);
                scan_step(x, one, wk, bk, v);
                int i = ii + j;
                if (i >= KK - 1) ob[(size_t)(i - (KK - 1)) * DD] = v[KK - 1];
            }
            xp += (size_t)8 * DD;
        }
#pragma unroll
        for (int j = 0; j < 8; j++) {
            scan_step(xb[j], one, wk, bk, v);
            ob[(size_t)(LL - 8 + j - (KK - 1)) * DD] = v[KK - 1];
        }
    } else {
        float* op = out + ((size_t)b * TOUT + (size_t)(c * LL - (KK - 1))) * DD + d;
        for (int ii = 0; ii < LL - 8; ii += 8) {
#pragma unroll
            for (int j = 0; j < 8; j++) {
                float x = xb[j];
                xb[j] = __ldg(xp + (size_t)j * DD);
                scan_step(x, one, wk, bk, v);
                op[(size_t)(ii + j) * DD] = v[KK - 1];
            }
            xp += (size_t)8 * DD;
        }
#pragma unroll
        for (int j = 0; j < 8; j++) {
            scan_step(xb[j], one, wk, bk, v);
            op[(size_t)(LL - 8 + j) * DD] = v[KK - 1];
        }
    }
}

// ---------------------------------------------------------------------------
extern "C" void kernel_launch(void* const* d_in, const int* in_sizes, int n_in,
                              void* d_out, int out_size)
{
    const float* X  = (const float*)d_in[0];
    const float* W  = (const float*)d_in[1];
    const float* Bv = (const float*)d_in[2];
    float* out = (float*)d_out;

    k1_transform<<<(NSEQ * (CC - 1)) / 32, 64>>>(X, W, Bv);
    k2_compose<<<(NSEQ * 8) / 128, 128>>>();
    k3_emit<<<(NSEQ * CC) / 128, 128>>>(X, W, Bv, out);
}

// round 10
// speedup vs baseline: 1.5062x; 1.0896x over previous
#include <cuda_runtime.h>
#include <math.h>

#define BB   8
#define TT   8192
#define DD   256
#define KK   8
#define CC   64
#define LL   (TT / CC)       // 128
#define NSEQ (BB * DD)       // 2048
#define TOUT (TT - KK + 1)   // 8185
#define QD   4               // K2 prefetch depth

// Scratch (static __device__ — no allocation). Plain scalar layout:
// element e of (chunk c, seq s) at g_trans[c][e][s] — coalesced over s.
__device__ float g_trans[CC][36][NSEQ];   // 18.9 MB
__device__ float g_entry[CC][KK][NSEQ];   // 4.2 MB

__host__ __device__ constexpr int coff(int j) { return j * 7 - j * (j - 1) / 2; }

// FFMA with IMMEDIATE 1.0 multiplier: src1-imm form has rt_SMSP=1 (2x reg form).
// d = a*1.0 + c  (bit-exact a + c).
#define FMAI(d, a, c) \
    asm("fma.rn.f32 %0, %1, 0f3F800000, %2;" : "=f"(d) : "f"(a), "f"(c))

__device__ __forceinline__ float chainmax(float m, float pred, float f)
{
    float t; FMAI(t, pred, f);
    return fmaxf(m, t);
}

// ---------------------------------------------------------------------------
// K1: column-split transform. Two warps per 32 (chunk,seq) pairs:
//   role 0: local vector v[0..7] + matrix cols 3,4,5,6 (18 states)
//   role 1: matrix cols 0,1,2                          (18 states)
// Chain adds use FFMA-imm; maxes are FMNMX (alu pipe, the hard floor).
// ---------------------------------------------------------------------------
__global__ void __launch_bounds__(64) k1_transform(
    const float* __restrict__ X,
    const float* __restrict__ W,
    const float* __restrict__ Bv)
{
    int lane = threadIdx.x & 31;
    int role = threadIdx.x >> 5;
    int pid  = blockIdx.x * 32 + lane;     // 0 .. NSEQ*(CC-1)-1
    int d = pid & (DD - 1);
    int q = pid >> 8;
    int b = q & (BB - 1);
    int c = q >> 3;                        // 0 .. CC-2
    int s = b * DD + d;

    const float NI = -INFINITY;

    float wk[KK], bk[KK];
#pragma unroll
    for (int k = 0; k < KK; k++) {
        wk[k] = __ldg(W + k * DD + d);
        bk[k] = __ldg(Bv + k * DD + d);
    }

    const float* xp = X + ((size_t)b * TT + (size_t)c * LL) * DD + d;

    float xb[8];
#pragma unroll
    for (int j = 0; j < 8; j++) xb[j] = __ldg(xp + (size_t)j * DD);
    xp += (size_t)8 * DD;

    if (role == 0) {
        float v[8], m3[4], m4[3], m5[2], m6;
#pragma unroll
        for (int k = 0; k < 8; k++) v[k] = NI;
#pragma unroll
        for (int i = 0; i < 4; i++) m3[i] = NI;
#pragma unroll
        for (int i = 0; i < 3; i++) m4[i] = NI;
        m5[0] = NI; m5[1] = NI; m6 = NI;

#define A_STEP(x) do {                                                   \
        float f[8];                                                      \
        _Pragma("unroll")                                                \
        for (int k = 0; k < 8; k++) f[k] = fmaf((x), wk[k], bk[k]);      \
        _Pragma("unroll")                                                \
        for (int k = 7; k >= 1; k--) v[k] = chainmax(v[k], v[k-1], f[k]); \
        v[0] = fmaxf(v[0], f[0]);                                        \
        m3[3] = chainmax(m3[3], m3[2], f[7]);                            \
        m3[2] = chainmax(m3[2], m3[1], f[6]);                            \
        m3[1] = chainmax(m3[1], m3[0], f[5]);                            \
        m3[0] = fmaxf(m3[0], f[4]);                                      \
        m4[2] = chainmax(m4[2], m4[1], f[7]);                            \
        m4[1] = chainmax(m4[1], m4[0], f[6]);                            \
        m4[0] = fmaxf(m4[0], f[5]);                                      \
        m5[1] = chainmax(m5[1], m5[0], f[7]);                            \
        m5[0] = fmaxf(m5[0], f[6]);                                      \
        m6    = fmaxf(m6, f[7]);                                         \
    } while (0)

        for (int ii = 0; ii < LL - 8; ii += 8) {
#pragma unroll
            for (int j = 0; j < 8; j++) {
                float x = xb[j];
                xb[j] = __ldg(xp + (size_t)j * DD);
                A_STEP(x);
            }
            xp += (size_t)8 * DD;
        }
#pragma unroll
        for (int j = 0; j < 8; j++) A_STEP(xb[j]);

#pragma unroll
        for (int k = 0; k < 8; k++) g_trans[c][k][s] = v[k];
#pragma unroll
        for (int i = 0; i < 4; i++) g_trans[c][8 + coff(3) + i][s] = m3[i];
#pragma unroll
        for (int i = 0; i < 3; i++) g_trans[c][8 + coff(4) + i][s] = m4[i];
#pragma unroll
        for (int i = 0; i < 2; i++) g_trans[c][8 + coff(5) + i][s] = m5[i];
        g_trans[c][8 + coff(6)][s] = m6;
    } else {
        float m0[7], m1[6], m2[5];
#pragma unroll
        for (int i = 0; i < 7; i++) m0[i] = NI;
#pragma unroll
        for (int i = 0; i < 6; i++) m1[i] = NI;
#pragma unroll
        for (int i = 0; i < 5; i++) m2[i] = NI;

#define B_STEP(x) do {                                                   \
        float f[8];                                                      \
        _Pragma("unroll")                                                \
        for (int k = 1; k < 8; k++) f[k] = fmaf((x), wk[k], bk[k]);      \
        _Pragma("unroll")                                                \
        for (int i = 6; i >= 1; i--) m0[i] = chainmax(m0[i], m0[i-1], f[i+1]); \
        m0[0] = fmaxf(m0[0], f[1]);                                      \
        _Pragma("unroll")                                                \
        for (int i = 5; i >= 1; i--) m1[i] = chainmax(m1[i], m1[i-1], f[i+2]); \
        m1[0] = fmaxf(m1[0], f[2]);                                      \
        _Pragma("unroll")                                                \
        for (int i = 4; i >= 1; i--) m2[i] = chainmax(m2[i], m2[i-1], f[i+3]); \
        m2[0] = fmaxf(m2[0], f[3]);                                      \
    } while (0)

        for (int ii = 0; ii < LL - 8; ii += 8) {
#pragma unroll
            for (int j = 0; j < 8; j++) {
                float x = xb[j];
                xb[j] = __ldg(xp + (size_t)j * DD);
                B_STEP(x);
            }
            xp += (size_t)8 * DD;
        }
#pragma unroll
        for (int j = 0; j < 8; j++) B_STEP(xb[j]);

#pragma unroll
        for (int i = 0; i < 7; i++) g_trans[c][8 + coff(0) + i][s] = m0[i];
#pragma unroll
        for (int i = 0; i < 6; i++) g_trans[c][8 + coff(1) + i][s] = m1[i];
#pragma unroll
        for (int i = 0; i < 5; i++) g_trans[c][8 + coff(2) + i][s] = m2[i];
    }
}

// ---------------------------------------------------------------------------
// K2: warp-parallel compose. 8 threads per sequence (thread = state k);
// v broadcast via shfl; depth-QD register prefetch hides L2 latency.
// ---------------------------------------------------------------------------
__global__ void __launch_bounds__(128) k2_compose()
{
    int t = blockIdx.x * blockDim.x + threadIdx.x;   // 0 .. NSEQ*8-1
    int k = t & 7;
    int s = t >> 3;
    int lane = threadIdx.x & 31;
    int gbase = lane & 24;
    const float NI = -INFINITY;

    int em[7];
#pragma unroll
    for (int j = 0; j < 7; j++)
        em[j] = 8 + coff(j) + k - j - 1;   // valid only when j < k

    const float* base = (const float*)g_trans;
    // element e of (c,s): base + ((size_t)c*36 + e)*NSEQ + s

    float pl[QD];
    float pm[QD][7];
#pragma unroll
    for (int u = 0; u < QD; u++) {
        int c = u;
        bool ok = (c <= CC - 2);
        pl[u] = ok ? __ldg(base + ((size_t)c * 36 + k) * NSEQ + s) : NI;
#pragma unroll
        for (int j = 0; j < 7; j++)
            pm[u][j] = (ok && j < k)
                ? __ldg(base + ((size_t)c * 36 + em[j]) * NSEQ + s) : NI;
    }

    float v = NI;

    for (int cb = 0; cb < CC; cb += QD) {
#pragma unroll
        for (int u = 0; u < QD; u++) {
            int c = cb + u;
            g_entry[c][k][s] = v;
            if (c == CC - 1) return;

            float vj[8];
#pragma unroll
            for (int j = 0; j < 8; j++)
                vj[j] = __shfl_sync(0xffffffffu, v, gbase + j);

            float nv = fmaxf(pl[u], v);
#pragma unroll
            for (int j = 0; j < 7; j++)
                nv = fmaxf(nv, vj[j] + pm[u][j]);
            v = nv;

            int cn = c + QD;
            bool ok = (cn <= CC - 2);
            pl[u] = ok ? __ldg(base + ((size_t)cn * 36 + k) * NSEQ + s) : NI;
#pragma unroll
            for (int j = 0; j < 7; j++)
                pm[u][j] = (ok && j < k)
                    ? __ldg(base + ((size_t)cn * 36 + em[j]) * NSEQ + s) : NI;
        }
    }
}

// ---------------------------------------------------------------------------
// K3: scalar re-scan, one thread per (chunk, seq); 8-deep x prefetch;
// chain adds as FFMA-imm.
// ---------------------------------------------------------------------------
__device__ __forceinline__ void scan_step(float x, const float* wk,
                                          const float* bk, float* v)
{
    float f[KK];
#pragma unroll
    for (int k = 0; k < KK; k++) f[k] = fmaf(x, wk[k], bk[k]);
#pragma unroll
    for (int k = KK - 1; k >= 1; k--) v[k] = chainmax(v[k], v[k - 1], f[k]);
    v[0] = fmaxf(v[0], f[0]);
}

__global__ void __launch_bounds__(128) k3_emit(
    const float* __restrict__ X,
    const float* __restrict__ W,
    const float* __restrict__ Bv,
    float* __restrict__ out)
{
    int tid = blockIdx.x * blockDim.x + threadIdx.x;   // 0 .. NSEQ*CC-1
    int d = tid & (DD - 1);
    int q = tid >> 8;
    int b = q & (BB - 1);
    int c = q >> 3;
    int s = b * DD + d;

    float wk[KK], bk[KK];
#pragma unroll
    for (int k = 0; k < KK; k++) {
        wk[k] = __ldg(W + k * DD + d);
        bk[k] = __ldg(Bv + k * DD + d);
    }

    float v[KK];
#pragma unroll
    for (int k = 0; k < KK; k++) v[k] = g_entry[c][k][s];

    const float* xp = X + ((size_t)b * TT + (size_t)c * LL) * DD + d;

    float xb[8];
#pragma unroll
    for (int j = 0; j < 8; j++) xb[j] = __ldg(xp + (size_t)j * DD);
    xp += (size_t)8 * DD;

    if (c == 0) {
        float* ob = out + (size_t)b * TOUT * DD + d;
        for (int ii = 0; ii < LL - 8; ii += 8) {
#pragma unroll
            for (int j = 0; j < 8; j++) {
                float x = xb[j];
                xb[j] = __ldg(xp + (size_t)j * DD);
                scan_step(x, wk, bk, v);
                int i = ii + j;
                if (i >= KK - 1) ob[(size_t)(i - (KK - 1)) * DD] = v[KK - 1];
            }
            xp += (size_t)8 * DD;
        }
#pragma unroll
        for (int j = 0; j < 8; j++) {
            scan_step(xb[j], wk, bk, v);
            ob[(size_t)(LL - 8 + j - (KK - 1)) * DD] = v[KK - 1];
        }
    } else {
        float* op = out + ((size_t)b * TOUT + (size_t)(c * LL - (KK - 1))) * DD + d;
        for (int ii = 0; ii < LL - 8; ii += 8) {
#pragma unroll
            for (int j = 0; j < 8; j++) {
                float x = xb[j];
                xb[j] = __ldg(xp + (size_t)j * DD);
                scan_step(x, wk, bk, v);
                op[(size_t)(ii + j) * DD] = v[KK - 1];
            }
            xp += (size_t)8 * DD;
        }
#pragma unroll
        for (int j = 0; j < 8; j++) {
            scan_step(xb[j], wk, bk, v);
            op[(size_t)(LL - 8 + j) * DD] = v[KK - 1];
        }
    }
}

// ---------------------------------------------------------------------------
extern "C" void kernel_launch(void* const* d_in, const int* in_sizes, int n_in,
                              void* d_out, int out_size)
{
    const float* X  = (const float*)d_in[0];
    const float* W  = (const float*)d_in[1];
    const float* Bv = (const float*)d_in[2];
    float* out = (float*)d_out;

    k1_transform<<<(NSEQ * (CC - 1)) / 32, 64>>>(X, W, Bv);
    k2_compose<<<(NSEQ * 8) / 128, 128>>>();
    k3_emit<<<(NSEQ * CC) / 128, 128>>>(X, W, Bv, out);
}